// round 4
// baseline (speedup 1.0000x reference)
#include <cuda_runtime.h>
#include <cstdint>

#define NS 13824            // D*H*W = 24*24*24
#define NB 2                // batch
#define NC 64               // channels
#define NVOX (NB * NS)      // 27648 voxels
#define PD 26               // padded dim
#define P3 (PD * PD * PD)   // 17576 padded voxels per batch

// q unpadded voxel-major [n][c]; k,v zero-padded [b][dp][hp][wp][c]
__device__ float g_q [NVOX * NC];
__device__ float g_kp[NB * P3 * NC];
__device__ float g_vp[NB * P3 * NC];

typedef unsigned long long u64;

__device__ __forceinline__ u64 pack2(float lo, float hi) {
    u64 r; asm("mov.b64 %0,{%1,%2};" : "=l"(r) : "f"(lo), "f"(hi)); return r;
}
__device__ __forceinline__ float2 unpack2(u64 v) {
    float2 r; asm("mov.b64 {%0,%1},%2;" : "=f"(r.x), "=f"(r.y) : "l"(v)); return r;
}
__device__ __forceinline__ u64 fma2(u64 a, u64 b, u64 c) {
    u64 d; asm("fma.rn.f32x2 %0,%1,%2,%3;" : "=l"(d) : "l"(a), "l"(b), "l"(c)); return d;
}

// ---------------------------------------------------------------------------
// Kernel 0: zero the padded borders of g_kp/g_vp (k_proj writes interior only).
// ---------------------------------------------------------------------------
__global__ __launch_bounds__(256) void k_zero_border()
{
    int idx = blockIdx.x * 256 + threadIdx.x;       // [0, NB*P3*16)
    int vox = idx >> 4;
    int c4  = (idx & 15) * 4;
    int r   = vox % P3;
    int dp = r / (PD * PD), hp = (r / PD) % PD, wp = r % PD;
    bool border = (dp == 0) | (dp == PD - 1) | (hp == 0) | (hp == PD - 1)
                | (wp == 0) | (wp == PD - 1);
    if (border) {
        float4 z = make_float4(0.f, 0.f, 0.f, 0.f);
        *(float4*)&g_kp[(long)vox * NC + c4] = z;
        *(float4*)&g_vp[(long)vox * NC + c4] = z;
    }
}

// ---------------------------------------------------------------------------
// Kernel 1: QKV projection. Block = 64 voxels, 8 warps.
// x staged in smem PRE-DUPLICATED (each value twice) so fma2 reads broadcast
// pairs straight from LDS -> zero pack MOVs in the inner loop.
// All three W tiles resident (transposed [j][c], pitch 68); one sync.
// q -> unpadded layout (scaled by hd^-0.5); k,v -> padded layout.
// ---------------------------------------------------------------------------
__global__ __launch_bounds__(256) void k_proj(
    const float* __restrict__ x,
    const float* __restrict__ Wq, const float* __restrict__ bq,
    const float* __restrict__ Wk, const float* __restrict__ bk,
    const float* __restrict__ Wv, const float* __restrict__ bv)
{
    extern __shared__ __align__(16) float smem[];
    float* Xs2 = smem;                 // 64 j * 128 (dup pairs)  = 32 KB
    float* WT  = smem + 64 * 128;      // 3 * 64 j * 68 (pitch)   = 52.2 KB

    const int tid  = threadIdx.x;
    const int lane = tid & 31;
    const int wid  = tid >> 5;
    const int tile = blockIdx.x;               // 0..431
    const int bb   = tile / (NS / 64);
    const int s0   = (tile % (NS / 64)) * 64;

    const float* xb = x + (long)bb * NC * NS + s0;

    // x tile: coalesced read, duplicated write
#pragma unroll
    for (int k = 0; k < 16; k++) {
        int idx = tid + k * 256;
        int j = idx >> 6, u = idx & 63;
        float v = xb[(long)j * NS + u];
        Xs2[j * 128 + 2 * u]     = v;
        Xs2[j * 128 + 2 * u + 1] = v;
    }
    // all three W tiles, transposed to [j][c]
    {
        const float* Wsrc[3] = {Wq, Wk, Wv};
#pragma unroll
        for (int m = 0; m < 3; m++) {
            const float* W = Wsrc[m];
            float* WTm = WT + m * 64 * 68;
#pragma unroll
            for (int k2 = 0; k2 < 16; k2++) {
                int idx = tid + k2 * 256;
                int c = idx >> 6, j = idx & 63;
                WTm[j * 68 + c] = W[idx];
            }
        }
    }
    __syncthreads();

    // lane tile: 4 channels x 4 voxels
    const int c0  = (wid & 1) * 32 + (lane >> 2) * 4;
    const int tv0 = (wid >> 1) * 16 + (lane & 3) * 4;

    // output addresses for the 4 voxels (w never wraps inside a 4-group)
    const int sA = s0 + tv0;
    const int d  = sA / 576, h = (sA / 24) % 24, w0 = sA % 24;
    const long nq  = (long)(bb * NS + sA) * NC + c0;
    const long npk = ((long)bb * P3 + (d + 1) * (PD * PD) + (h + 1) * PD + (w0 + 1)) * NC + c0;

    const float* bsrc[3] = {bq, bk, bv};

#pragma unroll
    for (int m = 0; m < 3; m++) {
        const float* WTm = WT + m * 64 * 68;
        const float4 bv4 = *(const float4*)&bsrc[m][c0];
        u64 acc[4][2];
#pragma unroll
        for (int t = 0; t < 4; t++) {
            acc[t][0] = pack2(bv4.x, bv4.y);
            acc[t][1] = pack2(bv4.z, bv4.w);
        }

#pragma unroll 8
        for (int j = 0; j < 64; j++) {
            ulonglong2 wv = *(const ulonglong2*)&WTm[j * 68 + c0];      // (w0,w1),(w2,w3)
            ulonglong2 xa = *(const ulonglong2*)&Xs2[j * 128 + tv0 * 2];     // dup x_t0, x_t1
            ulonglong2 xc = *(const ulonglong2*)&Xs2[j * 128 + tv0 * 2 + 4]; // dup x_t2, x_t3
            acc[0][0] = fma2(wv.x, xa.x, acc[0][0]);
            acc[0][1] = fma2(wv.y, xa.x, acc[0][1]);
            acc[1][0] = fma2(wv.x, xa.y, acc[1][0]);
            acc[1][1] = fma2(wv.y, xa.y, acc[1][1]);
            acc[2][0] = fma2(wv.x, xc.x, acc[2][0]);
            acc[2][1] = fma2(wv.y, xc.x, acc[2][1]);
            acc[3][0] = fma2(wv.x, xc.y, acc[3][0]);
            acc[3][1] = fma2(wv.y, xc.y, acc[3][1]);
        }

        if (m == 0) {
#pragma unroll
            for (int t = 0; t < 4; t++) {
                float2 a = unpack2(acc[t][0]);
                float2 b = unpack2(acc[t][1]);
                float4 o;                       // q scaled by hd^-0.5 = 0.25
                o.x = a.x * 0.25f; o.y = a.y * 0.25f;
                o.z = b.x * 0.25f; o.w = b.y * 0.25f;
                *(float4*)&g_q[nq + (long)t * NC] = o;
            }
        } else {
            float* g = (m == 1) ? g_kp : g_vp;
#pragma unroll
            for (int t = 0; t < 4; t++) {
                float2 a = unpack2(acc[t][0]);
                float2 b = unpack2(acc[t][1]);
                float4 o; o.x = a.x; o.y = a.y; o.z = b.x; o.w = b.y;
                *(float4*)&g[npk + (long)t * NC] = o;
            }
        }
    }
}

// ---------------------------------------------------------------------------
// Kernel 2: 3x3x3 local attention + residual.
// Voxel per 16 lanes; lane owns 4 contiguous channels (LDG.128, warp reads
// 512B contiguous). Quad = head; 2 shfls finish the 16-dim dot.
// Padded k/v layout -> NO border predication: 27 unconditional loads at
// compile-time offsets; padding gives logit 0 (exp=1) with zero v, exactly
// matching the reference softmax over zero-padded windows.
// ---------------------------------------------------------------------------
__global__ __launch_bounds__(256) void k_attn(
    const float* __restrict__ x, float* __restrict__ out)
{
    __shared__ float hs[64 * 17];

    const int tid  = threadIdx.x;
    const int lane = tid & 31;
    const int wid  = tid >> 5;

    const int n0 = blockIdx.x * 16;      // 16 voxels per block
    const int bb = n0 / NS;
    const int s0 = n0 % NS;

    const int half = lane >> 4;
    const int l4   = lane & 15;
    const int vloc = wid * 2 + half;
    const int s    = s0 + vloc;
    const int d = s / 576, h = (s / 24) % 24, w = s % 24;
    const int c0 = l4 * 4;               // quad (l4>>2) = head

    const long qa = (long)(bb * NS + s) * NC + c0;
    const ulonglong2 qv = *(const ulonglong2*)(g_q + qa);
    const u64 q01 = qv.x, q23 = qv.y;

    const long pb = ((long)bb * P3 + (d + 1) * (PD * PD) + (h + 1) * PD + (w + 1)) * NC + c0;
    const float* kb = g_kp + pb;
    const float* vb = g_vp + pb;

    u64 acc01 = 0ull, acc23 = 0ull;
    float lsum = 0.0f;

#pragma unroll
    for (int di = 0; di < 3; di++) {
#pragma unroll
        for (int hi = 0; hi < 3; hi++) {
#pragma unroll
            for (int wi = 0; wi < 3; wi++) {
                const int off = ((di - 1) * (PD * PD) + (hi - 1) * PD + (wi - 1)) * NC;
                ulonglong2 kk = *(const ulonglong2*)(kb + off);
                u64 dd = fma2(q01, kk.x, 0ull);
                dd = fma2(q23, kk.y, dd);
                float2 df = unpack2(dd);
                float sc = df.x + df.y;
                sc += __shfl_xor_sync(0xffffffffu, sc, 1);
                sc += __shfl_xor_sync(0xffffffffu, sc, 2);
                float p = __expf(sc);
                lsum += p;
                u64 p2 = pack2(p, p);
                ulonglong2 vv = *(const ulonglong2*)(vb + off);
                acc01 = fma2(p2, vv.x, acc01);
                acc23 = fma2(p2, vv.y, acc23);
            }
        }
    }

    const float inv = 1.0f / lsum;
    {
        float2 a = unpack2(acc01);
        float2 b = unpack2(acc23);
        hs[(c0 + 0) * 17 + vloc] = a.x * inv;
        hs[(c0 + 1) * 17 + vloc] = a.y * inv;
        hs[(c0 + 2) * 17 + vloc] = b.x * inv;
        hs[(c0 + 3) * 17 + vloc] = b.y * inv;
    }
    __syncthreads();

    // Coalesced channel-major output with residual add
#pragma unroll
    for (int k = 0; k < 4; k++) {
        int idx = tid + k * 256;
        int c = idx >> 4, t = idx & 15;
        long gi = ((long)bb * NC + c) * NS + s0 + t;
        out[gi] = hs[c * 17 + t] + x[gi];
    }
}

// ---------------------------------------------------------------------------
extern "C" void kernel_launch(void* const* d_in, const int* in_sizes, int n_in,
                              void* d_out, int out_size)
{
    const float* x  = (const float*)d_in[0];
    // d_in[1] = cemb (unused by reference forward)
    const float* Wq = (const float*)d_in[2];
    const float* bq = (const float*)d_in[3];
    const float* Wk = (const float*)d_in[4];
    const float* bk = (const float*)d_in[5];
    const float* Wv = (const float*)d_in[6];
    const float* bv = (const float*)d_in[7];
    float* out = (float*)d_out;

    const int smem_proj = (64 * 128 + 3 * 64 * 68) * sizeof(float);   // 84992 B
    static bool attr_set = false;
    if (!attr_set) {
        cudaFuncSetAttribute(k_proj, cudaFuncAttributeMaxDynamicSharedMemorySize, smem_proj);
        attr_set = true;
    }

    k_zero_border<<<(NB * P3 * 16) / 256, 256>>>();
    k_proj<<<NVOX / 64, 256, smem_proj>>>(x, Wq, bq, Wk, bk, Wv, bv);
    k_attn<<<NVOX / 16, 256>>>(x, out);
}

// round 5
// speedup vs baseline: 1.4937x; 1.4937x over previous
#include <cuda_runtime.h>
#include <cstdint>

#define NS 13824            // D*H*W = 24*24*24
#define NB 2                // batch
#define NC 64               // channels
#define NVOX (NB * NS)      // 27648 voxels
#define PD 26               // padded dim
#define PD2 (PD * PD)       // 676
#define P3 (PD * PD * PD)   // 17576 padded voxels per batch
#define NBORD 3752          // border voxels per batch = P3 - NS

// q unpadded voxel-major [n][c]; k,v zero-padded [b][dp][hp][wp][c]
__device__ float g_q [NVOX * NC];
__device__ float g_kp[NB * P3 * NC];
__device__ float g_vp[NB * P3 * NC];

typedef unsigned long long u64;

__device__ __forceinline__ u64 pack2(float lo, float hi) {
    u64 r; asm("mov.b64 %0,{%1,%2};" : "=l"(r) : "f"(lo), "f"(hi)); return r;
}
__device__ __forceinline__ float2 unpack2(u64 v) {
    float2 r; asm("mov.b64 {%0,%1},%2;" : "=f"(r.x), "=f"(r.y) : "l"(v)); return r;
}
__device__ __forceinline__ u64 fma2(u64 a, u64 b, u64 c) {
    u64 d; asm("fma.rn.f32x2 %0,%1,%2,%3;" : "=l"(d) : "l"(a), "l"(b), "l"(c)); return d;
}

// ---------------------------------------------------------------------------
// Kernel 0: zero ONLY the border voxels of g_kp/g_vp (direct enumeration,
// no masked full-volume scan). 16 threads per border voxel (one float4 each).
// Regions: A: dp in {0,25} (1352) ; B: dp 1..24, hp in {0,25} (1248) ;
//          C: dp 1..24, hp 1..24, wp in {0,25} (1152). Total 3752.
// ---------------------------------------------------------------------------
__global__ __launch_bounds__(256) void k_zero_border()
{
    int idx = blockIdx.x * 256 + threadIdx.x;   // [0, NB*NBORD*16) exactly
    int t  = idx >> 4;
    int c4 = (idx & 15) * 4;
    int bb = t / NBORD;
    int r  = t % NBORD;

    int dp, hp, wp;
    if (r < 1352) {                   // faces dp = 0 / 25
        dp = (r >= 676) ? 25 : 0;
        int q = (r >= 676) ? r - 676 : r;
        hp = q / PD; wp = q % PD;
    } else if (r < 2600) {            // faces hp = 0 / 25
        int q = r - 1352;
        dp = 1 + q / 52;
        int q2 = q % 52;
        hp = (q2 >= 26) ? 25 : 0;
        wp = (q2 >= 26) ? q2 - 26 : q2;
    } else {                          // faces wp = 0 / 25
        int q = r - 2600;
        dp = 1 + q / 48;
        int q2 = q % 48;
        hp = 1 + (q2 >> 1);
        wp = (q2 & 1) ? 25 : 0;
    }

    long vox = (long)bb * P3 + dp * PD2 + hp * PD + wp;
    float4 z = make_float4(0.f, 0.f, 0.f, 0.f);
    *(float4*)&g_kp[vox * NC + c4] = z;
    *(float4*)&g_vp[vox * NC + c4] = z;
}

// ---------------------------------------------------------------------------
// Kernel 1: QKV projection (R3 kernel, stores k/v into padded layout).
// Block = 64 voxels of one batch, 8 warps. Warp tile 32ch x 16vox,
// lane tile 4ch x 4vox. Per j: LDS.128 W (conflict-free) + LDS.128 x (bcast).
// ---------------------------------------------------------------------------
__global__ __launch_bounds__(256) void k_proj(
    const float* __restrict__ x,
    const float* __restrict__ Wq, const float* __restrict__ bq,
    const float* __restrict__ Wk, const float* __restrict__ bk,
    const float* __restrict__ Wv, const float* __restrict__ bv)
{
    __shared__ __align__(16) float WTs[64 * 68];   // WTs[j*68 + c] = W[c][j]
    __shared__ __align__(16) float Xs[64 * 64];    // Xs[j*64 + t]

    const int tid  = threadIdx.x;
    const int lane = tid & 31;
    const int wid  = tid >> 5;
    const int tile = blockIdx.x;               // 0..431
    const int bb   = tile / (NS / 64);
    const int s0   = (tile % (NS / 64)) * 64;

    const float* xb = x + (long)bb * NC * NS + s0;

#pragma unroll
    for (int k = 0; k < 16; k++) {
        int idx = tid + k * 256;
        int j = idx >> 6, u = idx & 63;
        Xs[j * 64 + u] = xb[(long)j * NS + u];
    }

    const int c0  = (wid & 1) * 32 + (lane >> 2) * 4;
    const int tv0 = (wid >> 1) * 16 + (lane & 3) * 4;

    // output addresses for the 4-voxel run (w-aligned: never wraps a row)
    const int sA = s0 + tv0;
    const int d  = sA / 576, h = (sA / 24) % 24, w0 = sA % 24;
    const long nq  = (long)(bb * NS + sA) * NC + c0;
    const long npk = ((long)bb * P3 + (d + 1) * PD2 + (h + 1) * PD + (w0 + 1)) * NC + c0;

    const float* Wsrc[3] = {Wq, Wk, Wv};
    const float* bsrc[3] = {bq, bk, bv};

#pragma unroll
    for (int m = 0; m < 3; m++) {
        __syncthreads();
        const float* W = Wsrc[m];
#pragma unroll
        for (int k2 = 0; k2 < 16; k2++) {
            int idx = tid + k2 * 256;
            int c = idx >> 6, j = idx & 63;
            WTs[j * 68 + c] = W[idx];
        }
        __syncthreads();

        const float4 bv4 = *(const float4*)&bsrc[m][c0];
        u64 acc[4][2];
#pragma unroll
        for (int t = 0; t < 4; t++) {
            acc[t][0] = pack2(bv4.x, bv4.y);
            acc[t][1] = pack2(bv4.z, bv4.w);
        }

#pragma unroll 8
        for (int j = 0; j < 64; j++) {
            ulonglong2 w = *(const ulonglong2*)&WTs[j * 68 + c0];
            float4 xv = *(const float4*)&Xs[j * 64 + tv0];
            u64 xd0 = pack2(xv.x, xv.x);
            u64 xd1 = pack2(xv.y, xv.y);
            u64 xd2 = pack2(xv.z, xv.z);
            u64 xd3 = pack2(xv.w, xv.w);
            acc[0][0] = fma2(w.x, xd0, acc[0][0]);
            acc[0][1] = fma2(w.y, xd0, acc[0][1]);
            acc[1][0] = fma2(w.x, xd1, acc[1][0]);
            acc[1][1] = fma2(w.y, xd1, acc[1][1]);
            acc[2][0] = fma2(w.x, xd2, acc[2][0]);
            acc[2][1] = fma2(w.y, xd2, acc[2][1]);
            acc[3][0] = fma2(w.x, xd3, acc[3][0]);
            acc[3][1] = fma2(w.y, xd3, acc[3][1]);
        }

        if (m == 0) {
#pragma unroll
            for (int t = 0; t < 4; t++) {
                float2 a = unpack2(acc[t][0]);
                float2 b = unpack2(acc[t][1]);
                float4 o;                     // q pre-scaled by hd^-0.5 = 0.25
                o.x = a.x * 0.25f; o.y = a.y * 0.25f;
                o.z = b.x * 0.25f; o.w = b.y * 0.25f;
                *(float4*)&g_q[nq + (long)t * NC] = o;
            }
        } else {
            float* g = (m == 1) ? g_kp : g_vp;
#pragma unroll
            for (int t = 0; t < 4; t++) {
                float2 a = unpack2(acc[t][0]);
                float2 b = unpack2(acc[t][1]);
                float4 o; o.x = a.x; o.y = a.y; o.z = b.x; o.w = b.y;
                *(float4*)&g[npk + (long)t * NC] = o;
            }
        }
    }
}

// ---------------------------------------------------------------------------
// Kernel 2: 3x3x3 local attention + residual. Padded k/v -> branchless.
// Thread handles FOUR consecutive-w queries (sliding window): per (di,hi)
// plane, the 6-wide k/v row is loaded once; each k_j/v_j serves up to 3
// queries -> 27 loads/query (vs 54) and 4 independent softmax chains for ILP.
// 16 lanes per query-group; lane owns 4 contiguous channels (LDG.128,
// warp reads 2x512B contiguous). Quad = head; 2 shfls finish the dot.
// Single-pass softmax (shift-invariant; logits O(1), exp(0)=1 for padding).
// ---------------------------------------------------------------------------
__global__ __launch_bounds__(256) void k_attn(
    const float* __restrict__ x, float* __restrict__ out)
{
    __shared__ float hs[64 * 65];

    const int tid  = threadIdx.x;
    const int lane = tid & 31;
    const int wid  = tid >> 5;

    const int n0 = blockIdx.x * 64;      // 64 voxels per block, same batch
    const int bb = n0 / NS;
    const int s0 = n0 % NS;

    const int half = lane >> 4;
    const int l4   = lane & 15;
    const int grp  = wid * 2 + half;     // query group 0..15
    const int sg   = s0 + grp * 4;       // first of 4 queries (w-aligned)
    const int d = sg / 576, h = (sg / 24) % 24, w0 = sg % 24;
    const int c0 = l4 * 4;               // quad (l4>>2) = head

    // q for the 4 queries
    u64 q01[4], q23[4];
    {
        const long qa = (long)(bb * NS + sg) * NC + c0;
#pragma unroll
        for (int i = 0; i < 4; i++) {
            ulonglong2 qv = *(const ulonglong2*)(g_q + qa + (long)i * NC);
            q01[i] = qv.x; q23[i] = qv.y;
        }
    }

    // padded base at (d+1, h+1, w0): w-position j covers padded w0..w0+5,
    // i.e. query i's neighbors are j in {i, i+1, i+2}. Always in-range.
    const long pb = ((long)bb * P3 + (d + 1) * PD2 + (h + 1) * PD + w0) * NC + c0;

    u64 acc01[4], acc23[4];
    float lsum[4];
#pragma unroll
    for (int i = 0; i < 4; i++) { acc01[i] = 0ull; acc23[i] = 0ull; lsum[i] = 0.0f; }

#pragma unroll
    for (int dh = 0; dh < 9; dh++) {
        const int di = dh / 3 - 1, hi = dh % 3 - 1;
        const long rb = pb + (long)(di * PD2 + hi * PD) * NC;
        const float* kb = g_kp + rb;
        const float* vb = g_vp + rb;
#pragma unroll
        for (int j = 0; j < 6; j++) {
            ulonglong2 kk = *(const ulonglong2*)(kb + j * NC);
            ulonglong2 vv = *(const ulonglong2*)(vb + j * NC);
            const int ilo = (j - 2 > 0) ? j - 2 : 0;
            const int ihi = (j < 3) ? j : 3;
#pragma unroll
            for (int i = ilo; i <= ihi; i++) {
                u64 dd = fma2(q01[i], kk.x, 0ull);
                dd = fma2(q23[i], kk.y, dd);
                float2 df = unpack2(dd);
                float sc = df.x + df.y;
                sc += __shfl_xor_sync(0xffffffffu, sc, 1);
                sc += __shfl_xor_sync(0xffffffffu, sc, 2);
                float p = __expf(sc);
                lsum[i] += p;
                u64 p2 = pack2(p, p);
                acc01[i] = fma2(p2, vv.x, acc01[i]);
                acc23[i] = fma2(p2, vv.y, acc23[i]);
            }
        }
    }

#pragma unroll
    for (int i = 0; i < 4; i++) {
        const float inv = 1.0f / lsum[i];
        float2 a = unpack2(acc01[i]);
        float2 b = unpack2(acc23[i]);
        const int col = grp * 4 + i;
        hs[(c0 + 0) * 65 + col] = a.x * inv;
        hs[(c0 + 1) * 65 + col] = a.y * inv;
        hs[(c0 + 2) * 65 + col] = b.x * inv;
        hs[(c0 + 3) * 65 + col] = b.y * inv;
    }
    __syncthreads();

    // Coalesced channel-major output with residual add (64 vox x 64 ch)
#pragma unroll
    for (int k = 0; k < 16; k++) {
        int idx = tid + k * 256;
        int c = idx >> 6, t = idx & 63;
        long gi = ((long)bb * NC + c) * NS + s0 + t;
        out[gi] = hs[c * 65 + t] + x[gi];
    }
}

// ---------------------------------------------------------------------------
extern "C" void kernel_launch(void* const* d_in, const int* in_sizes, int n_in,
                              void* d_out, int out_size)
{
    const float* x  = (const float*)d_in[0];
    // d_in[1] = cemb (unused by reference forward)
    const float* Wq = (const float*)d_in[2];
    const float* bq = (const float*)d_in[3];
    const float* Wk = (const float*)d_in[4];
    const float* bk = (const float*)d_in[5];
    const float* Wv = (const float*)d_in[6];
    const float* bv = (const float*)d_in[7];
    float* out = (float*)d_out;

    k_zero_border<<<(NB * NBORD * 16) / 256, 256>>>();   // 120064/256 = 469 exact
    k_proj<<<NVOX / 64, 256>>>(x, Wq, bq, Wk, bk, Wv, bv);
    k_attn<<<NVOX / 64, 256>>>(x, out);
}

// round 6
// speedup vs baseline: 1.5411x; 1.0317x over previous
#include <cuda_runtime.h>
#include <cstdint>

#define NS 13824            // D*H*W = 24*24*24
#define NB 2                // batch
#define NC 64               // channels
#define NVOX (NB * NS)      // 27648 voxels
#define PD 26               // padded dim
#define PD2 (PD * PD)       // 676
#define P3 (PD * PD * PD)   // 17576 padded voxels per batch
#define NBORD 3752          // border voxels per batch = P3 - NS
#define NPROJ (NVOX / 64)   // 432 projection blocks
#define NZERO ((NB * NBORD * 16) / 256)   // 469 border-zero blocks

// q unpadded voxel-major [n][c]; k,v zero-padded [b][dp][hp][wp][c]
__device__ float g_q [NVOX * NC];
__device__ float g_kp[NB * P3 * NC];
__device__ float g_vp[NB * P3 * NC];

typedef unsigned long long u64;

__device__ __forceinline__ u64 pack2(float lo, float hi) {
    u64 r; asm("mov.b64 %0,{%1,%2};" : "=l"(r) : "f"(lo), "f"(hi)); return r;
}
__device__ __forceinline__ float2 unpack2(u64 v) {
    float2 r; asm("mov.b64 {%0,%1},%2;" : "=f"(r.x), "=f"(r.y) : "l"(v)); return r;
}
__device__ __forceinline__ u64 fma2(u64 a, u64 b, u64 c) {
    u64 d; asm("fma.rn.f32x2 %0,%1,%2,%3;" : "=l"(d) : "l"(a), "l"(b), "l"(c)); return d;
}

// ---------------------------------------------------------------------------
// Kernel 1: QKV projection + (tail blocks) border zeroing.
// Blocks [0, NPROJ): projection, 64 voxels each (R5 kernel unchanged).
// Blocks [NPROJ, NPROJ+NZERO): zero the 3752 border voxels/batch of g_kp/g_vp
// (direct enumeration). These tiny blocks hide entirely under the proj work.
// ---------------------------------------------------------------------------
__global__ __launch_bounds__(256) void k_proj(
    const float* __restrict__ x,
    const float* __restrict__ Wq, const float* __restrict__ bq,
    const float* __restrict__ Wk, const float* __restrict__ bk,
    const float* __restrict__ Wv, const float* __restrict__ bv)
{
    __shared__ __align__(16) float WTs[64 * 68];   // WTs[j*68 + c] = W[c][j]
    __shared__ __align__(16) float Xs[64 * 64];    // Xs[j*64 + t]

    const int tid = threadIdx.x;

    if (blockIdx.x >= NPROJ) {
        // ---- border zeroing tail blocks ----
        int idx = (blockIdx.x - NPROJ) * 256 + tid;   // [0, NB*NBORD*16)
        int t  = idx >> 4;
        int c4 = (idx & 15) * 4;
        int bb = t / NBORD;
        int r  = t % NBORD;

        int dp, hp, wp;
        if (r < 1352) {                   // faces dp = 0 / 25
            dp = (r >= 676) ? 25 : 0;
            int q = (r >= 676) ? r - 676 : r;
            hp = q / PD; wp = q % PD;
        } else if (r < 2600) {            // faces hp = 0 / 25
            int q = r - 1352;
            dp = 1 + q / 52;
            int q2 = q % 52;
            hp = (q2 >= 26) ? 25 : 0;
            wp = (q2 >= 26) ? q2 - 26 : q2;
        } else {                          // faces wp = 0 / 25
            int q = r - 2600;
            dp = 1 + q / 48;
            int q2 = q % 48;
            hp = 1 + (q2 >> 1);
            wp = (q2 & 1) ? 25 : 0;
        }

        long vox = (long)bb * P3 + dp * PD2 + hp * PD + wp;
        float4 z = make_float4(0.f, 0.f, 0.f, 0.f);
        *(float4*)&g_kp[vox * NC + c4] = z;
        *(float4*)&g_vp[vox * NC + c4] = z;
        return;
    }

    // ---- projection blocks ----
    const int lane = tid & 31;
    const int wid  = tid >> 5;
    const int tile = blockIdx.x;               // 0..431
    const int bb   = tile / (NS / 64);
    const int s0   = (tile % (NS / 64)) * 64;

    const float* xb = x + (long)bb * NC * NS + s0;

#pragma unroll
    for (int k = 0; k < 16; k++) {
        int idx = tid + k * 256;
        int j = idx >> 6, u = idx & 63;
        Xs[j * 64 + u] = xb[(long)j * NS + u];
    }

    const int c0  = (wid & 1) * 32 + (lane >> 2) * 4;
    const int tv0 = (wid >> 1) * 16 + (lane & 3) * 4;

    // output addresses for the 4-voxel run (w-aligned: never wraps a row)
    const int sA = s0 + tv0;
    const int d  = sA / 576, h = (sA / 24) % 24, w0 = sA % 24;
    const long nq  = (long)(bb * NS + sA) * NC + c0;
    const long npk = ((long)bb * P3 + (d + 1) * PD2 + (h + 1) * PD + (w0 + 1)) * NC + c0;

    const float* Wsrc[3] = {Wq, Wk, Wv};
    const float* bsrc[3] = {bq, bk, bv};

#pragma unroll
    for (int m = 0; m < 3; m++) {
        __syncthreads();
        const float* W = Wsrc[m];
#pragma unroll
        for (int k2 = 0; k2 < 16; k2++) {
            int idx = tid + k2 * 256;
            int c = idx >> 6, j = idx & 63;
            WTs[j * 68 + c] = W[idx];
        }
        __syncthreads();

        const float4 bv4 = *(const float4*)&bsrc[m][c0];
        u64 acc[4][2];
#pragma unroll
        for (int t = 0; t < 4; t++) {
            acc[t][0] = pack2(bv4.x, bv4.y);
            acc[t][1] = pack2(bv4.z, bv4.w);
        }

#pragma unroll 8
        for (int j = 0; j < 64; j++) {
            ulonglong2 w = *(const ulonglong2*)&WTs[j * 68 + c0];
            float4 xv = *(const float4*)&Xs[j * 64 + tv0];
            u64 xd0 = pack2(xv.x, xv.x);
            u64 xd1 = pack2(xv.y, xv.y);
            u64 xd2 = pack2(xv.z, xv.z);
            u64 xd3 = pack2(xv.w, xv.w);
            acc[0][0] = fma2(w.x, xd0, acc[0][0]);
            acc[0][1] = fma2(w.y, xd0, acc[0][1]);
            acc[1][0] = fma2(w.x, xd1, acc[1][0]);
            acc[1][1] = fma2(w.y, xd1, acc[1][1]);
            acc[2][0] = fma2(w.x, xd2, acc[2][0]);
            acc[2][1] = fma2(w.y, xd2, acc[2][1]);
            acc[3][0] = fma2(w.x, xd3, acc[3][0]);
            acc[3][1] = fma2(w.y, xd3, acc[3][1]);
        }

        if (m == 0) {
#pragma unroll
            for (int t = 0; t < 4; t++) {
                float2 a = unpack2(acc[t][0]);
                float2 b = unpack2(acc[t][1]);
                float4 o;                     // q pre-scaled by hd^-0.5 = 0.25
                o.x = a.x * 0.25f; o.y = a.y * 0.25f;
                o.z = b.x * 0.25f; o.w = b.y * 0.25f;
                *(float4*)&g_q[nq + (long)t * NC] = o;
            }
        } else {
            float* g = (m == 1) ? g_kp : g_vp;
#pragma unroll
            for (int t = 0; t < 4; t++) {
                float2 a = unpack2(acc[t][0]);
                float2 b = unpack2(acc[t][1]);
                float4 o; o.x = a.x; o.y = a.y; o.z = b.x; o.w = b.y;
                *(float4*)&g[npk + (long)t * NC] = o;
            }
        }
    }
}

// ---------------------------------------------------------------------------
// Kernel 2: 3x3x3 local attention + residual. Padded k/v -> branchless.
// Thread handles FOUR consecutive-w queries (sliding window). Per (di,hi)
// plane: phase 1 batches all 6 k-row loads (MLP=6), computes the 12 (i,j)
// score/exp pairs into a p-buffer; phase 2 batches 6 v-row loads and applies.
// 16 lanes per query-group; lane owns 4 contiguous channels (LDG.128).
// Quad = head; 2 shfls finish the 16-dim dot. Single-pass softmax
// (shift-invariant; logits O(1); padding contributes exp(0)=1, zero v).
// ---------------------------------------------------------------------------
__global__ __launch_bounds__(256) void k_attn(
    const float* __restrict__ x, float* __restrict__ out)
{
    __shared__ float hs[64 * 65];

    const int tid  = threadIdx.x;
    const int lane = tid & 31;
    const int wid  = tid >> 5;

    const int n0 = blockIdx.x * 64;      // 64 voxels per block, same batch
    const int bb = n0 / NS;
    const int s0 = n0 % NS;

    const int half = lane >> 4;
    const int l4   = lane & 15;
    const int grp  = wid * 2 + half;     // query group 0..15
    const int sg   = s0 + grp * 4;       // first of 4 queries (w-aligned)
    const int d = sg / 576, h = (sg / 24) % 24, w0 = sg % 24;
    const int c0 = l4 * 4;               // quad (l4>>2) = head

    // q for the 4 queries
    u64 q01[4], q23[4];
    {
        const long qa = (long)(bb * NS + sg) * NC + c0;
#pragma unroll
        for (int i = 0; i < 4; i++) {
            ulonglong2 qv = *(const ulonglong2*)(g_q + qa + (long)i * NC);
            q01[i] = qv.x; q23[i] = qv.y;
        }
    }

    // padded base at (d+1, h+1, w0): row j covers padded w0+j; query i's
    // neighbors are rows j in {i, i+1, i+2}. Always in-range (padded).
    const long pb = ((long)bb * P3 + (d + 1) * PD2 + (h + 1) * PD + w0) * NC + c0;

    u64 acc01[4], acc23[4];
    float lsum[4];
#pragma unroll
    for (int i = 0; i < 4; i++) { acc01[i] = 0ull; acc23[i] = 0ull; lsum[i] = 0.0f; }

#pragma unroll
    for (int dh = 0; dh < 9; dh++) {
        const int di = dh / 3 - 1, hi = dh % 3 - 1;
        const long rb = pb + (long)(di * PD2 + hi * PD) * NC;
        const float* kb = g_kp + rb;
        const float* vb = g_vp + rb;

        // phase 1: batch all k-row loads, compute p for the 12 (i,j) pairs
        ulonglong2 kr[6];
#pragma unroll
        for (int j = 0; j < 6; j++) kr[j] = *(const ulonglong2*)(kb + j * NC);

        float pv[12];
        int pi = 0;
#pragma unroll
        for (int j = 0; j < 6; j++) {
            const int ilo = (j - 2 > 0) ? j - 2 : 0;
            const int ihi = (j < 3) ? j : 3;
#pragma unroll
            for (int i = ilo; i <= ihi; i++) {
                u64 dd = fma2(q01[i], kr[j].x, 0ull);
                dd = fma2(q23[i], kr[j].y, dd);
                float2 df = unpack2(dd);
                float sc = df.x + df.y;
                sc += __shfl_xor_sync(0xffffffffu, sc, 1);
                sc += __shfl_xor_sync(0xffffffffu, sc, 2);
                float p = __expf(sc);
                lsum[i] += p;
                pv[pi++] = p;
            }
        }

        // phase 2: batch all v-row loads, apply weights
        ulonglong2 vr[6];
#pragma unroll
        for (int j = 0; j < 6; j++) vr[j] = *(const ulonglong2*)(vb + j * NC);

        pi = 0;
#pragma unroll
        for (int j = 0; j < 6; j++) {
            const int ilo = (j - 2 > 0) ? j - 2 : 0;
            const int ihi = (j < 3) ? j : 3;
#pragma unroll
            for (int i = ilo; i <= ihi; i++) {
                u64 p2 = pack2(pv[pi], pv[pi]);
                pi++;
                acc01[i] = fma2(p2, vr[j].x, acc01[i]);
                acc23[i] = fma2(p2, vr[j].y, acc23[i]);
            }
        }
    }

#pragma unroll
    for (int i = 0; i < 4; i++) {
        const float inv = 1.0f / lsum[i];
        float2 a = unpack2(acc01[i]);
        float2 b = unpack2(acc23[i]);
        const int col = grp * 4 + i;
        hs[(c0 + 0) * 65 + col] = a.x * inv;
        hs[(c0 + 1) * 65 + col] = a.y * inv;
        hs[(c0 + 2) * 65 + col] = b.x * inv;
        hs[(c0 + 3) * 65 + col] = b.y * inv;
    }
    __syncthreads();

    // Coalesced channel-major output with residual add (64 vox x 64 ch)
#pragma unroll
    for (int k = 0; k < 16; k++) {
        int idx = tid + k * 256;
        int c = idx >> 6, t = idx & 63;
        long gi = ((long)bb * NC + c) * NS + s0 + t;
        out[gi] = hs[c * 65 + t] + x[gi];
    }
}

// ---------------------------------------------------------------------------
extern "C" void kernel_launch(void* const* d_in, const int* in_sizes, int n_in,
                              void* d_out, int out_size)
{
    const float* x  = (const float*)d_in[0];
    // d_in[1] = cemb (unused by reference forward)
    const float* Wq = (const float*)d_in[2];
    const float* bq = (const float*)d_in[3];
    const float* Wk = (const float*)d_in[4];
    const float* bk = (const float*)d_in[5];
    const float* Wv = (const float*)d_in[6];
    const float* bv = (const float*)d_in[7];
    float* out = (float*)d_out;

    k_proj<<<NPROJ + NZERO, 256>>>(x, Wq, bq, Wk, bk, Wv, bv);
    k_attn<<<NVOX / 64, 256>>>(x, out);
}